// round 1
// baseline (speedup 1.0000x reference)
#include <cuda_runtime.h>

#define MAX_KNOTS 2048   // table staging capacity (actual N_KNOTS = 1025)

__global__ void interp1d_kernel(const float4* __restrict__ b4,
                                const float* __restrict__ xs,
                                const float* __restrict__ ys,
                                float4* __restrict__ out4,
                                int n4,            // number of 4-point groups
                                int n_knots,
                                float inv_dis)     // = n_knots - 1
{
    __shared__ float sxs[MAX_KNOTS];
    __shared__ float sys[MAX_KNOTS];

    // Cooperative stage of the knot tables into shared memory.
    for (int t = threadIdx.x; t < n_knots; t += blockDim.x) {
        sxs[t] = xs[t];
        sys[t] = ys[t];
    }
    __syncthreads();

    const int imax = n_knots - 2;
    int g      = blockIdx.x * blockDim.x + threadIdx.x;
    int stride = gridDim.x * blockDim.x;

    for (; g < n4; g += stride) {
        // Two float4 loads = 4 points' (x, y) pairs; we use .x and .z (the x coords).
        float4 p0 = b4[2 * g];
        float4 p1 = b4[2 * g + 1];

        float xv[4] = { p0.x, p0.z, p1.x, p1.z };
        float r[4];

        #pragma unroll
        for (int k = 0; k < 4; k++) {
            float x  = xv[k];
            int   i  = (int)(x * inv_dis + 1e-5f);   // x/dis, dis exact power of two
            i        = min(i, imax);
            float x0 = sxs[i];
            float x1 = sxs[i + 1];
            float y0 = sys[i];
            float y1 = sys[i + 1];
            float w  = x1 - x0;
            r[k] = ((x1 - x) * y0 + (x - x0) * y1) / w;
        }

        out4[g] = make_float4(r[0], r[1], r[2], r[3]);
    }
}

extern "C" void kernel_launch(void* const* d_in, const int* in_sizes, int n_in,
                              void* d_out, int out_size)
{
    const float* b  = (const float*)d_in[0];   // [N_POINTS, 2] f32
    const float* xs = (const float*)d_in[1];   // [N_KNOTS]     f32
    const float* ys = (const float*)d_in[2];   // [N_KNOTS]     f32
    float*       o  = (float*)d_out;           // [N_POINTS]    f32

    int n_points = in_sizes[0] / 2;
    int n_knots  = in_sizes[1];
    int n4       = n_points / 4;               // N_POINTS = 16777216, divisible by 4

    float inv_dis = (float)(n_knots - 1);

    const int threads = 256;
    int blocks = (n4 + threads - 1) / threads;

    interp1d_kernel<<<blocks, threads>>>(
        (const float4*)b, xs, ys, (float4*)o, n4, n_knots, inv_dis);
}

// round 2
// speedup vs baseline: 1.6027x; 1.6027x over previous
#include <cuda_runtime.h>

#define MAX_INTERVALS 2048   // capacity (actual = 1024)

__global__ void interp1d_kernel(const float4* __restrict__ b4,
                                const float* __restrict__ xs,
                                const float* __restrict__ ys,
                                float4* __restrict__ out4,
                                int n4,           // number of 4-point groups
                                int n_knots,
                                float dis,        // 1/(n_knots-1), exact power of two
                                float inv_dis)    // n_knots-1
{
    // Per-interval coefficients: {y0, slope}. One LDS.64 per point replaces
    // four scattered LDS.32 + one fp32 division.
    __shared__ float2 coef[MAX_INTERVALS];

    const int n_int = n_knots - 1;
    for (int t = threadIdx.x; t < n_int; t += blockDim.x) {
        float x0 = xs[t];
        float x1 = xs[t + 1];
        float y0 = ys[t];
        float y1 = ys[t + 1];
        coef[t] = make_float2(y0, (y1 - y0) / (x1 - x0));
    }
    __syncthreads();

    const int imax   = n_knots - 2;
    const int stride = gridDim.x * blockDim.x;

    for (int g = blockIdx.x * blockDim.x + threadIdx.x; g < n4; g += stride) {
        // Two float4 loads = 4 points' (x, y) pairs; x coords are .x and .z.
        float4 p0 = b4[2 * g];
        float4 p1 = b4[2 * g + 1];

        float xv[4] = { p0.x, p0.z, p1.x, p1.z };
        float r[4];

        #pragma unroll
        for (int k = 0; k < 4; k++) {
            float x = xv[k];
            int   i = min((int)(x * inv_dis + 1e-5f), imax);
            float2 c = coef[i];                 // single LDS.64
            float dx = x - (float)i * dis;      // i*dis exact; == x - xs[i]
            r[k] = fmaf(dx, c.y, c.x);          // y0 + (x-x0)*slope
        }

        out4[g] = make_float4(r[0], r[1], r[2], r[3]);
    }
}

extern "C" void kernel_launch(void* const* d_in, const int* in_sizes, int n_in,
                              void* d_out, int out_size)
{
    const float* b  = (const float*)d_in[0];   // [N_POINTS, 2] f32
    const float* xs = (const float*)d_in[1];   // [N_KNOTS]     f32
    const float* ys = (const float*)d_in[2];   // [N_KNOTS]     f32
    float*       o  = (float*)d_out;           // [N_POINTS]    f32

    int n_points = in_sizes[0] / 2;
    int n_knots  = in_sizes[1];
    int n4       = n_points / 4;               // N_POINTS divisible by 4

    float inv_dis = (float)(n_knots - 1);
    float dis     = 1.0f / inv_dis;

    const int threads = 256;
    // Persistent-style grid: 148 SMs x 8 CTAs -> table setup cost (divisions +
    // xs/ys reloads) drops ~14x vs one block per tile.
    int blocks = 148 * 8;
    int max_blocks = (n4 + threads - 1) / threads;
    if (blocks > max_blocks) blocks = max_blocks;

    interp1d_kernel<<<blocks, threads>>>(
        (const float4*)b, xs, ys, (float4*)o, n4, n_knots, dis, inv_dis);
}